// round 3
// baseline (speedup 1.0000x reference)
#include <cuda_runtime.h>
#include <cuda_bf16.h>

// EdgeEncoding: out[h,i,j] = sum_e coeff[e] * enc[node[e], h], enc = edge_attr@W.T + b.
// Factorized: out[h,p] = g[p].W[h] + b[h]*s[p];  g[p]=sum c_e*edge_attr[node_e], s[p]=sum c_e.
// pair_idx sorted over the real prefix; padding tail has coeff==0 (never flushed).
// Avg segment length ~17 entries -> per-thread serial chunks with boundary atomics.

#define NNODES 768
#define NN (NNODES * NNODES)   // 589824 pairs
#define NH 32

#define BT 256                  // threads per block, pass 1
#define ITEMS 32                // entries per thread (128B contiguous per thread)
#define TILE (BT * ITEMS)       // 8192 entries per block

// Fused scratch: g (float4[NN]) followed by s (float[NN]). One flat zero pass.
__device__ __align__(16) float d_buf[NN * 5];
#define D_G ((float4*)d_buf)
#define D_S (d_buf + (size_t)NN * 4)

// ---------------------------------------------------------------------------
// Kernel 0: zero the fused buffer. NN*5 floats = 737280 float4 slots (exact
// multiple of 256*2) -> branch-free, 2 float4 per thread.
// ---------------------------------------------------------------------------
#define ZV 2
__global__ void __launch_bounds__(256) zero_kernel() {
    int i = (blockIdx.x * 256 + threadIdx.x) * ZV;
    float4 z = make_float4(0.f, 0.f, 0.f, 0.f);
    float4* p = reinterpret_cast<float4*>(d_buf);
    p[i] = z;
    p[i + 1] = z;
}

// Branchless predicated flush: no BSSY/BSYNC, just 2 predicated STG.
__device__ __forceinline__ void pred_flush(int doit, int key,
                                           float ax, float ay, float az, float aw, float as)
{
    unsigned long long ga = (unsigned long long)(D_G + key);
    unsigned long long sa = (unsigned long long)(D_S + key);
    asm volatile(
        "{\n\t.reg .pred p;\n\t"
        "setp.ne.s32 p, %0, 0;\n\t"
        "@p st.global.v4.f32 [%1], {%3, %4, %5, %6};\n\t"
        "@p st.global.f32 [%2], %7;\n\t}"
        :: "r"(doit), "l"(ga), "l"(sa),
           "f"(ax), "f"(ay), "f"(az), "f"(aw), "f"(as));
}

__device__ __forceinline__ void flush_maybe_shared(bool shared_seg, int key,
                                                   float ax, float ay, float az,
                                                   float aw, float as)
{
    float* gp = reinterpret_cast<float*>(&D_G[key]);
    if (shared_seg) {
        atomicAdd(gp + 0, ax); atomicAdd(gp + 1, ay);
        atomicAdd(gp + 2, az); atomicAdd(gp + 3, aw);
        atomicAdd(&D_S[key], as);
    } else {
        D_G[key] = make_float4(ax, ay, az, aw);
        D_S[key] = as;
    }
}

// ---------------------------------------------------------------------------
// Kernel 1: segmented reduction, direct global int4 loads (no staging).
// ---------------------------------------------------------------------------
__global__ void __launch_bounds__(BT) pass1_kernel(
    const int*   __restrict__ pair_idx,
    const int*   __restrict__ node_idx,
    const float* __restrict__ coeff,
    const float* __restrict__ edge_attr,   // [768,4]
    int M)
{
    const int tile0 = blockIdx.x * TILE;

    // Padding early-exit: real coeffs strictly positive, padding is a suffix.
    if (tile0 > 0 && __ldg(&coeff[tile0]) == 0.f) return;

    __shared__ float4 sea[NNODES];   // 12 KB
    const int tid = threadIdx.x;
    for (int i = tid; i < NNODES; i += BT)
        sea[i] = reinterpret_cast<const float4*>(edge_attr)[i];
    __syncthreads();

    const int e0 = tile0 + tid * ITEMS;
    if (e0 >= M) return;

    const bool full = (e0 + ITEMS <= M);

    int prevk = (e0 > 0) ? __ldg(&pair_idx[e0 - 1]) : -3;
    int nextk = (e0 + ITEMS < M) ? __ldg(&pair_idx[e0 + ITEMS]) : -3;

    int   cur = __ldg(&pair_idx[e0]);
    float ax = 0.f, ay = 0.f, az = 0.f, aw = 0.f, as = 0.f;
    int   segidx = 0;
    int   s0key = 0;
    float s0x = 0.f, s0y = 0.f, s0z = 0.f, s0w = 0.f, s0s = 0.f;

    const int4*   pv4 = reinterpret_cast<const int4*>(pair_idx + e0);
    const int4*   nv4 = reinterpret_cast<const int4*>(node_idx + e0);
    const float4* cv4 = reinterpret_cast<const float4*>(coeff + e0);

    #pragma unroll
    for (int bch = 0; bch < ITEMS / 4; bch++) {
        int   pk[4], nk[4];
        float ck[4];
        if (full) {
            int4   pv = __ldg(&pv4[bch]);
            int4   nv = __ldg(&nv4[bch]);
            float4 cv = __ldg(&cv4[bch]);
            pk[0] = pv.x; pk[1] = pv.y; pk[2] = pv.z; pk[3] = pv.w;
            nk[0] = nv.x; nk[1] = nv.y; nk[2] = nv.z; nk[3] = nv.w;
            ck[0] = cv.x; ck[1] = cv.y; ck[2] = cv.z; ck[3] = cv.w;
        } else {
            #pragma unroll
            for (int k = 0; k < 4; k++) {
                int g = e0 + bch * 4 + k;
                bool ok = (g < M);
                pk[k] = ok ? __ldg(&pair_idx[g]) : -1;
                nk[k] = ok ? __ldg(&node_idx[g]) : 0;
                ck[k] = ok ? __ldg(&coeff[g])    : 0.f;
            }
        }

        #pragma unroll
        for (int k = 0; k < 4; k++) {
            int  key = pk[k];
            bool neq = (key != cur);

            // Interior segments (segidx>0) are provably exclusive -> predicated STG.
            int doflush = (int)(neq & (segidx != 0) & (as != 0.f));
            pred_flush(doflush, cur, ax, ay, az, aw, as);

            // Stash segment 0 (may be shared with previous chunk).
            bool stash = neq & (segidx == 0);
            s0key = stash ? cur : s0key;
            s0x = stash ? ax : s0x;  s0y = stash ? ay : s0y;
            s0z = stash ? az : s0z;  s0w = stash ? aw : s0w;
            s0s = stash ? as : s0s;

            segidx += (int)neq;

            float  c  = ck[k];
            float4 ea = sea[nk[k]];
            ax = fmaf(c, ea.x, neq ? 0.f : ax);
            ay = fmaf(c, ea.y, neq ? 0.f : ay);
            az = fmaf(c, ea.z, neq ? 0.f : az);
            aw = fmaf(c, ea.w, neq ? 0.f : aw);
            as = c + (neq ? 0.f : as);
            cur = key;
        }
    }

    // Open tail segment: may be shared with the next chunk (and with the
    // previous one if it's the only segment in this chunk).
    if (as != 0.f && cur >= 0) {
        bool shared_seg = (nextk == cur) || (segidx == 0 && prevk == cur);
        flush_maybe_shared(shared_seg, cur, ax, ay, az, aw, as);
    }
    // Stashed segment 0 (closed on the right inside this chunk).
    if (segidx > 0 && s0s != 0.f) {
        flush_maybe_shared(prevk == s0key, s0key, s0x, s0y, s0z, s0w, s0s);
    }
}

// ---------------------------------------------------------------------------
// Kernel 2: expand g/s -> 32 channels, plane-major coalesced float4 stores.
// ---------------------------------------------------------------------------
#define BT2 256
#define PP  4

__global__ void __launch_bounds__(BT2) pass2_kernel(
    const float* __restrict__ W,   // [32,4]
    const float* __restrict__ b,   // [32]
    float* __restrict__ out)       // [32, 768*768]
{
    __shared__ float sW[NH * 4];
    __shared__ float sb[NH];
    int tid = threadIdx.x;
    if (tid < NH * 4) sW[tid] = W[tid];
    if (tid < NH)     sb[tid] = b[tid];
    __syncthreads();

    int p = (blockIdx.x * BT2 + tid) * PP;
    float4 g0 = D_G[p + 0];
    float4 g1 = D_G[p + 1];
    float4 g2 = D_G[p + 2];
    float4 g3 = D_G[p + 3];
    float4 sv = reinterpret_cast<const float4*>(D_S)[p >> 2];

    #pragma unroll 4
    for (int h = 0; h < NH; h++) {
        float w0 = sW[4 * h + 0], w1 = sW[4 * h + 1];
        float w2 = sW[4 * h + 2], w3 = sW[4 * h + 3];
        float bh = sb[h];
        float4 r;
        r.x = fmaf(g0.x, w0, fmaf(g0.y, w1, fmaf(g0.z, w2, fmaf(g0.w, w3, sv.x * bh))));
        r.y = fmaf(g1.x, w0, fmaf(g1.y, w1, fmaf(g1.z, w2, fmaf(g1.w, w3, sv.y * bh))));
        r.z = fmaf(g2.x, w0, fmaf(g2.y, w1, fmaf(g2.z, w2, fmaf(g2.w, w3, sv.z * bh))));
        r.w = fmaf(g3.x, w0, fmaf(g3.y, w1, fmaf(g3.z, w2, fmaf(g3.w, w3, sv.w * bh))));
        reinterpret_cast<float4*>(out)[(h * NN + p) >> 2] = r;
    }
}

// ---------------------------------------------------------------------------
// kernel_launch
// ---------------------------------------------------------------------------
extern "C" void kernel_launch(void* const* d_in, const int* in_sizes, int n_in,
                              void* d_out, int out_size)
{
    const float* edge_attr = nullptr;
    const float* W = nullptr;
    const float* b = nullptr;
    const int*   pair = nullptr;
    const int*   node = nullptr;
    const float* coeff = nullptr;
    int M = 0;
    int bigSeen = 0;

    for (int i = 0; i < n_in; i++) {
        int s = in_sizes[i];
        if (s == NNODES * 4)      edge_attr = (const float*)d_in[i];
        else if (s == NH * 4)     W = (const float*)d_in[i];
        else if (s == NH)         b = (const float*)d_in[i];
        else if (s >= 1000000) {
            if (bigSeen == 0)      pair  = (const int*)d_in[i];
            else if (bigSeen == 1) node  = (const int*)d_in[i];
            else if (bigSeen == 2) { coeff = (const float*)d_in[i]; M = s; }
            bigSeen++;
        }
    }

    // NN*5 floats = 737280 float4 slots; 256 threads * ZV -> 1440 blocks exact.
    int zgrid = (NN * 5 / 4) / (256 * ZV);
    zero_kernel<<<zgrid, 256>>>();

    int grid1 = (M + TILE - 1) / TILE;
    pass1_kernel<<<grid1, BT>>>(pair, node, coeff, edge_attr, M);

    int grid2 = NN / (BT2 * PP);
    pass2_kernel<<<grid2, BT2>>>(W, b, (float*)d_out);
}

// round 4
// speedup vs baseline: 1.4783x; 1.4783x over previous
#include <cuda_runtime.h>
#include <cuda_bf16.h>

// EdgeEncoding: out[h,i,j] = sum_e coeff[e]*enc[node[e],h], enc = edge_attr@W.T+b.
// Factorized: out[h,p] = g[p].W[h] + b[h]*s[p]; g[p]=sum c_e*edge_attr[node_e], s[p]=sum c_e.
// pair_idx sorted over the real prefix (keys contiguous); padding tail coeff==0.
// Pass1: warp-cooperative segmented reduce-by-key. Lane l owns 4 consecutive
// entries (coalesced int4). Sorted keys => equal-tkey lanes are contiguous, so a
// conditional Kogge-Stone shuffle scan sums trailing partials across lanes.
// Only warp-boundary-crossing segments need atomics; boundary sharing is simply
// (key == prevk / nextk). Padding segments have s==0 and are never flushed.

#define NNODES 768
#define NN (NNODES * NNODES)   // 589824
#define NH 32

#define BT 256                  // threads/block pass1 (8 warps)
#define TILE (BT * 4)           // 1024 entries per block, 128 per warp

// Fused scratch: g (float4[NN]) then s (float[NN]); zeroed by one memset node.
__device__ __align__(16) float d_buf[NN * 5];
#define D_G ((float4*)d_buf)
#define D_S (d_buf + (size_t)NN * 4)

// Branchless predicated flush (exclusive interior segments): no BSSY/BSYNC.
__device__ __forceinline__ void pred_flush(int doit, int key,
                                           float ax, float ay, float az, float aw, float as)
{
    unsigned long long ga = (unsigned long long)(D_G + key);
    unsigned long long sa = (unsigned long long)(D_S + key);
    asm volatile(
        "{\n\t.reg .pred p;\n\t"
        "setp.ne.s32 p, %0, 0;\n\t"
        "@p st.global.v4.f32 [%1], {%3, %4, %5, %6};\n\t"
        "@p st.global.f32 [%2], %7;\n\t}"
        :: "r"(doit), "l"(ga), "l"(sa),
           "f"(ax), "f"(ay), "f"(az), "f"(aw), "f"(as));
}

__device__ __forceinline__ void flush_maybe_shared(bool shared_seg, int key,
                                                   float ax, float ay, float az,
                                                   float aw, float as)
{
    float* gp = reinterpret_cast<float*>(&D_G[key]);
    if (shared_seg) {
        atomicAdd(gp + 0, ax); atomicAdd(gp + 1, ay);
        atomicAdd(gp + 2, az); atomicAdd(gp + 3, aw);
        atomicAdd(&D_S[key], as);
    } else {
        D_G[key] = make_float4(ax, ay, az, aw);
        D_S[key] = as;
    }
}

// ---------------------------------------------------------------------------
// Pass 1
// ---------------------------------------------------------------------------
__global__ void __launch_bounds__(BT) pass1_kernel(
    const int*   __restrict__ pair_idx,
    const int*   __restrict__ node_idx,
    const float* __restrict__ coeff,
    const float* __restrict__ edge_attr,   // [768,4]
    int M)
{
    const int tile0 = blockIdx.x * TILE;
    // Skip all-padding blocks (real coeffs strictly positive, padding is a suffix).
    if (tile0 > 0 && tile0 < M && __ldg(&coeff[tile0]) == 0.f) return;

    __shared__ float4 sea[NNODES];   // 12 KB
    const int tid = threadIdx.x;
    for (int i = tid; i < NNODES; i += BT)
        sea[i] = reinterpret_cast<const float4*>(edge_attr)[i];
    __syncthreads();

    const int lane = tid & 31;
    const int base = tile0 + (tid >> 5) * 128;    // warp's 128-entry range
    const int e0   = base + lane * 4;
    const unsigned FULL = 0xffffffffu;

    // --- load 4 entries (coalesced int4) ---
    int pk0, pk1, pk2, pk3, nk0, nk1, nk2, nk3;
    float c0, c1, c2, c3;
    if (e0 + 3 < M) {
        int4   pv = __ldg(reinterpret_cast<const int4*>(pair_idx + e0));
        int4   nv = __ldg(reinterpret_cast<const int4*>(node_idx + e0));
        float4 cv = __ldg(reinterpret_cast<const float4*>(coeff + e0));
        pk0 = pv.x; pk1 = pv.y; pk2 = pv.z; pk3 = pv.w;
        nk0 = nv.x; nk1 = nv.y; nk2 = nv.z; nk3 = nv.w;
        c0 = cv.x; c1 = cv.y; c2 = cv.z; c3 = cv.w;
    } else {
        int   tp[4]; int tn[4]; float tc[4];
        #pragma unroll
        for (int k = 0; k < 4; k++) {
            int g = e0 + k;
            bool ok = (g < M);
            tp[k] = ok ? __ldg(&pair_idx[g]) : 0;
            tn[k] = ok ? __ldg(&node_idx[g]) : 0;
            tc[k] = ok ? __ldg(&coeff[g])    : 0.f;
        }
        pk0 = tp[0]; pk1 = tp[1]; pk2 = tp[2]; pk3 = tp[3];
        nk0 = tn[0]; nk1 = tn[1]; nk2 = tn[2]; nk3 = tn[3];
        c0 = tc[0]; c1 = tc[1]; c2 = tc[2]; c3 = tc[3];
    }

    // warp neighbor keys
    int pv0 = 0;
    if (lane == 0)  pv0 = (base > 0) ? __ldg(&pair_idx[base - 1]) : -3;
    const int prevk = __shfl_sync(FULL, pv0, 0);
    int nv31 = 0;
    if (lane == 31) nv31 = (base + 128 < M) ? __ldg(&pair_idx[base + 128]) : -3;
    const int nextk = __shfl_sync(FULL, nv31, 31);

    // --- local scan of 4 items ---
    const int headkey = pk0;
    int   cur = pk0;
    float4 ea = sea[nk0];
    float ax = c0 * ea.x, ay = c0 * ea.y, az = c0 * ea.z, aw = c0 * ea.w, as = c0;
    int   segcnt = 0;
    int   hkey = 0;
    float hx = 0.f, hy = 0.f, hz = 0.f, hw = 0.f, hs = 0.f;

    int kk_[3] = {pk1, pk2, pk3};
    int nn_[3] = {nk1, nk2, nk3};
    float cc_[3] = {c1, c2, c3};
    #pragma unroll
    for (int k = 0; k < 3; k++) {
        int  key = kk_[k];
        bool neq = (key != cur);
        // interior segment (2nd+ change): fully inside lane => exclusive store
        int doflush = (int)(neq & (segcnt > 0) & (as != 0.f));
        pred_flush(doflush, cur, ax, ay, az, aw, as);
        // stash first segment partial (connects left)
        bool stash = neq & (segcnt == 0);
        hkey = stash ? cur : hkey;
        hx = stash ? ax : hx; hy = stash ? ay : hy; hz = stash ? az : hz;
        hw = stash ? aw : hw; hs = stash ? as : hs;
        segcnt += (int)neq;
        float  c  = cc_[k];
        float4 e  = sea[nn_[k]];
        ax = fmaf(c, e.x, neq ? 0.f : ax);
        ay = fmaf(c, e.y, neq ? 0.f : ay);
        az = fmaf(c, e.z, neq ? 0.f : az);
        aw = fmaf(c, e.w, neq ? 0.f : aw);
        as = c + (neq ? 0.f : as);
        cur = key;
    }
    const int tkey = cur;   // trailing segment key; (ax..as) = trailing partial

    // --- conditional Kogge-Stone: sum trailing partials over equal-tkey runs ---
    #pragma unroll
    for (int d = 1; d < 32; d <<= 1) {
        int   sk = __shfl_up_sync(FULL, tkey, d);
        float sx = __shfl_up_sync(FULL, ax, d);
        float sy = __shfl_up_sync(FULL, ay, d);
        float sz = __shfl_up_sync(FULL, az, d);
        float sw = __shfl_up_sync(FULL, aw, d);
        float ss = __shfl_up_sync(FULL, as, d);
        bool add = (lane >= d) && (sk == tkey);
        ax += add ? sx : 0.f;
        ay += add ? sy : 0.f;
        az += add ? sz : 0.f;
        aw += add ? sw : 0.f;
        as += add ? ss : 0.f;
    }

    // neighbors of the scanned values
    int   tkp = __shfl_up_sync(FULL, tkey, 1);
    float ypx = __shfl_up_sync(FULL, ax, 1);
    float ypy = __shfl_up_sync(FULL, ay, 1);
    float ypz = __shfl_up_sync(FULL, az, 1);
    float ypw = __shfl_up_sync(FULL, aw, 1);
    float yps = __shfl_up_sync(FULL, as, 1);
    int   hkn = __shfl_down_sync(FULL, headkey, 1);

    // 1) head-close flush (impure lanes): first segment closed inside this lane.
    //    total = head partial + carry from trailing chain of previous lanes.
    if (segcnt > 0) {
        bool cge = (lane > 0) && (hkey == tkp);
        float fx = hx + (cge ? ypx : 0.f);
        float fy = hy + (cge ? ypy : 0.f);
        float fz = hz + (cge ? ypz : 0.f);
        float fw = hw + (cge ? ypw : 0.f);
        float fs = hs + (cge ? yps : 0.f);
        if (fs != 0.f)
            flush_maybe_shared(hkey == prevk, hkey, fx, fy, fz, fw, fs);
    }
    // 2) trailing-chain close: lane l owns the full within-warp sum for tkey if
    //    the segment ends at this lane's last item.
    bool closes = (lane == 31) || (hkn != tkey);
    if (closes && as != 0.f) {
        bool shared_seg = (tkey == prevk) || ((lane == 31) && (tkey == nextk));
        flush_maybe_shared(shared_seg, tkey, ax, ay, az, aw, as);
    }
}

// ---------------------------------------------------------------------------
// Pass 2: expand g/s -> 32 channels, plane-major coalesced float4 stores.
// ---------------------------------------------------------------------------
#define BT2 256
#define PP  4

__global__ void __launch_bounds__(BT2) pass2_kernel(
    const float* __restrict__ W,   // [32,4]
    const float* __restrict__ b,   // [32]
    float* __restrict__ out)       // [32, 768*768]
{
    __shared__ float sW[NH * 4];
    __shared__ float sb[NH];
    int tid = threadIdx.x;
    if (tid < NH * 4) sW[tid] = W[tid];
    if (tid < NH)     sb[tid] = b[tid];
    __syncthreads();

    int p = (blockIdx.x * BT2 + tid) * PP;
    float4 g0 = D_G[p + 0];
    float4 g1 = D_G[p + 1];
    float4 g2 = D_G[p + 2];
    float4 g3 = D_G[p + 3];
    float4 sv = reinterpret_cast<const float4*>(D_S)[p >> 2];

    #pragma unroll 4
    for (int h = 0; h < NH; h++) {
        float w0 = sW[4 * h + 0], w1 = sW[4 * h + 1];
        float w2 = sW[4 * h + 2], w3 = sW[4 * h + 3];
        float bh = sb[h];
        float4 r;
        r.x = fmaf(g0.x, w0, fmaf(g0.y, w1, fmaf(g0.z, w2, fmaf(g0.w, w3, sv.x * bh))));
        r.y = fmaf(g1.x, w0, fmaf(g1.y, w1, fmaf(g1.z, w2, fmaf(g1.w, w3, sv.y * bh))));
        r.z = fmaf(g2.x, w0, fmaf(g2.y, w1, fmaf(g2.z, w2, fmaf(g2.w, w3, sv.z * bh))));
        r.w = fmaf(g3.x, w0, fmaf(g3.y, w1, fmaf(g3.z, w2, fmaf(g3.w, w3, sv.w * bh))));
        reinterpret_cast<float4*>(out)[(h * NN + p) >> 2] = r;
    }
}

// ---------------------------------------------------------------------------
// kernel_launch
// ---------------------------------------------------------------------------
extern "C" void kernel_launch(void* const* d_in, const int* in_sizes, int n_in,
                              void* d_out, int out_size)
{
    const float* edge_attr = nullptr;
    const float* W = nullptr;
    const float* b = nullptr;
    const int*   pair = nullptr;
    const int*   node = nullptr;
    const float* coeff = nullptr;
    int M = 0;
    int bigSeen = 0;

    for (int i = 0; i < n_in; i++) {
        int s = in_sizes[i];
        if (s == NNODES * 4)      edge_attr = (const float*)d_in[i];
        else if (s == NH * 4)     W = (const float*)d_in[i];
        else if (s == NH)         b = (const float*)d_in[i];
        else if (s >= 1000000) {
            if (bigSeen == 0)      pair  = (const int*)d_in[i];
            else if (bigSeen == 1) node  = (const int*)d_in[i];
            else if (bigSeen == 2) { coeff = (const float*)d_in[i]; M = s; }
            bigSeen++;
        }
    }

    // Zero scratch with a graph-capturable memset node (no allocation).
    void* bufp = nullptr;
    cudaGetSymbolAddress(&bufp, d_buf);
    cudaMemsetAsync(bufp, 0, sizeof(float) * (size_t)NN * 5);

    int grid1 = (M + TILE - 1) / TILE;
    pass1_kernel<<<grid1, BT>>>(pair, node, coeff, edge_attr, M);

    int grid2 = NN / (BT2 * PP);
    pass2_kernel<<<grid2, BT2>>>(W, b, (float*)d_out);
}